// round 7
// baseline (speedup 1.0000x reference)
#include <cuda_runtime.h>
#include <math.h>

namespace cfg {
constexpr int B  = 32;
constexpr int S  = 512;
constexpr int E  = 512;
constexpr int T  = 24;
constexpr int H  = 2;
constexpr int HD = E / H;          // 256
constexpr int BS = B * S;          // 16384
}

// ---------------- scratch (static device globals; no allocation) ------------
__device__ float g_qkv[(size_t)cfg::B * cfg::S * 3 * cfg::E];
__device__ float g_scores[(size_t)cfg::B * cfg::H * cfg::S * cfg::S];
__device__ float g_attn[(size_t)cfg::B * cfg::S * cfg::E];
__device__ float g_dec [(size_t)cfg::B * cfg::S * cfg::E];
__device__ float g_em  [(size_t)cfg::B * cfg::S * cfg::T];
__device__ float g_xr  [(size_t)cfg::B * cfg::S * cfg::E];       // rounded x
__device__ float g_wr  [(size_t)4 * cfg::E * cfg::E + cfg::T * cfg::E]; // rounded Win|Wout|crf_w
__device__ float g_num [cfg::B];
__device__ float g_den [cfg::B];
__device__ float g_msum[cfg::B];

// ---------------- helpers ----------------------------------------------------
__device__ __forceinline__ unsigned f2tf(unsigned rawf32) {
    unsigned u;
    asm("cvt.rna.tf32.f32 %0, %1;" : "=r"(u) : "f"(__uint_as_float(rawf32)));
    return u;
}
__device__ __forceinline__ float roundtf(float x) {
    return __uint_as_float(f2tf(__float_as_uint(x)));
}

__device__ __forceinline__ void mma_tf32(float* d, const unsigned* a, const unsigned* b) {
    asm volatile(
        "mma.sync.aligned.m16n8k8.row.col.f32.tf32.tf32.f32 "
        "{%0,%1,%2,%3}, {%4,%5,%6,%7}, {%8,%9}, {%0,%1,%2,%3};"
        : "+f"(d[0]), "+f"(d[1]), "+f"(d[2]), "+f"(d[3])
        : "r"(a[0]), "r"(a[1]), "r"(a[2]), "r"(a[3]), "r"(b[0]), "r"(b[1]));
}

__device__ __forceinline__ void cp16(unsigned dst, const float* src, bool pred) {
    int sz = pred ? 16 : 0;
    asm volatile("cp.async.cg.shared.global [%0], [%1], 16, %2;"
                 :: "r"(dst), "l"(src), "r"(sz));
}
__device__ __forceinline__ void cp_commit() {
    asm volatile("cp.async.commit_group;");
}
template<int N0>
__device__ __forceinline__ void cp_wait() {
    asm volatile("cp.async.wait_group %0;" :: "n"(N0));
}

// ---------------- elementwise tf32 pre-round ---------------------------------
__global__ void round_tf32_kernel(const float* __restrict__ in, float* __restrict__ out, int n4)
{
    int i = blockIdx.x * blockDim.x + threadIdx.x;
    if (i < n4) {
        float4 v = ((const float4*)in)[i];
        v.x = roundtf(v.x); v.y = roundtf(v.y);
        v.z = roundtf(v.z); v.w = roundtf(v.w);
        ((float4*)out)[i] = v;
    }
}

// ---------------- TF32 tensor-core GEMM: C = alpha*A*op(B) + bias -----------
// A: M x K (lda).  TRANSB: B is N x K (ldb) -> C=A*B^T.  else B is K x N (ldb).
// CVT: apply cvt.rna.tf32 at fragment load (needed when inputs not pre-rounded).
// RND: round output to tf32 at epilogue (when consumer is exclusively a GEMM).
template<bool TRANSB, bool RELU, bool CVT, bool RND>
__global__ __launch_bounds__(256, 2)
void tgemm(const float* __restrict__ A, const float* __restrict__ Bp,
           float* __restrict__ C, const float* __restrict__ bias,
           int M, int N, int K, int lda, int ldb, int ldc, float alpha,
           int HH, int sab, int sah, int sbb, int sbh, int scb, int sch)
{
    constexpr int BK    = 16;
    constexpr int ASTR  = 20;
    constexpr int BSTRT = 20;
    constexpr int BSTRN = 136;

    int z = blockIdx.z;
    A  += (size_t)(z / HH) * sab + (size_t)(z % HH) * sah;
    Bp += (size_t)(z / HH) * sbb + (size_t)(z % HH) * sbh;
    C  += (size_t)(z / HH) * scb + (size_t)(z % HH) * sch;

    __shared__ unsigned As[2][128 * ASTR];
    __shared__ unsigned Bs[2][128 * ASTR];

    const int tid  = threadIdx.x;
    const int warp = tid >> 5;
    const int lane = tid & 31;
    const int qid  = lane >> 2;
    const int cid  = lane & 3;

    const int m0 = blockIdx.y * 128;
    const int n0 = blockIdx.x * 128;
    const int wm = (warp >> 2) * 64;
    const int wn = (warp & 3) * 32;

    const int arow = tid >> 1;
    const int ak   = (tid & 1) * 8;
    const int bkk  = tid >> 4;
    const int bnn  = (tid & 15) * 8;

    float acc[4][4][4];
#pragma unroll
    for (int i = 0; i < 4; i++)
#pragma unroll
        for (int j = 0; j < 4; j++)
#pragma unroll
            for (int r = 0; r < 4; r++) acc[i][j][r] = 0.f;

    const int nt = K / BK;

    const unsigned as_d0 = (unsigned)__cvta_generic_to_shared(&As[0][arow * ASTR + ak]);
    const unsigned as_d1 = (unsigned)__cvta_generic_to_shared(&As[1][arow * ASTR + ak]);
    unsigned bs_d0, bs_d1;
    if (TRANSB) {
        bs_d0 = (unsigned)__cvta_generic_to_shared(&Bs[0][arow * BSTRT + ak]);
        bs_d1 = (unsigned)__cvta_generic_to_shared(&Bs[1][arow * BSTRT + ak]);
    } else {
        bs_d0 = (unsigned)__cvta_generic_to_shared(&Bs[0][bkk * BSTRN + bnn]);
        bs_d1 = (unsigned)__cvta_generic_to_shared(&Bs[1][bkk * BSTRN + bnn]);
    }
    const bool bval = TRANSB ? (n0 + arow < N) : (n0 + bnn < N);

#define LOADG(k0, buf)                                                         \
    {                                                                          \
        const float* Ap = A + (size_t)(m0 + arow) * lda + (k0) + ak;           \
        unsigned ad = (buf) ? as_d1 : as_d0;                                   \
        cp16(ad,      Ap,     true);                                           \
        cp16(ad + 16, Ap + 4, true);                                           \
        unsigned bd = (buf) ? bs_d1 : bs_d0;                                   \
        if (TRANSB) {                                                          \
            const float* Bq = Bp + (size_t)(n0 + arow) * ldb + (k0) + ak;      \
            cp16(bd,      Bq,     bval);                                       \
            cp16(bd + 16, Bq + 4, bval);                                       \
        } else {                                                               \
            const float* Bq = Bp + (size_t)((k0) + bkk) * ldb + n0 + bnn;      \
            cp16(bd,      Bq,     bval);                                       \
            cp16(bd + 16, Bq + 4, bval);                                       \
        }                                                                      \
    }

    LOADG(0, 0);
    cp_commit();

    for (int t = 0; t < nt; t++) {
        const int cur = t & 1;
        if (t + 1 < nt) LOADG((t + 1) * BK, cur ^ 1);
        cp_commit();
        cp_wait<1>();
        __syncthreads();

        const unsigned* Ab = As[cur];
        const unsigned* Bb = Bs[cur];
#pragma unroll
        for (int ks = 0; ks < 2; ks++) {
            const int k0 = ks * 8;
            unsigned af[4][4], bf[4][2];
#pragma unroll
            for (int mt = 0; mt < 4; mt++) {
                const int rb = wm + mt * 16 + qid;
                unsigned a0 = Ab[(rb    ) * ASTR + k0 + cid];
                unsigned a1 = Ab[(rb + 8) * ASTR + k0 + cid];
                unsigned a2 = Ab[(rb    ) * ASTR + k0 + cid + 4];
                unsigned a3 = Ab[(rb + 8) * ASTR + k0 + cid + 4];
                if (CVT) { a0 = f2tf(a0); a1 = f2tf(a1); a2 = f2tf(a2); a3 = f2tf(a3); }
                af[mt][0] = a0; af[mt][1] = a1; af[mt][2] = a2; af[mt][3] = a3;
            }
#pragma unroll
            for (int ntl = 0; ntl < 4; ntl++) {
                const int nb = wn + ntl * 8 + qid;
                unsigned b0, b1;
                if (TRANSB) {
                    b0 = Bb[nb * BSTRT + k0 + cid];
                    b1 = Bb[nb * BSTRT + k0 + cid + 4];
                } else {
                    b0 = Bb[(k0 + cid    ) * BSTRN + nb];
                    b1 = Bb[(k0 + cid + 4) * BSTRN + nb];
                }
                if (CVT) { b0 = f2tf(b0); b1 = f2tf(b1); }
                bf[ntl][0] = b0; bf[ntl][1] = b1;
            }
#pragma unroll
            for (int mt = 0; mt < 4; mt++)
#pragma unroll
                for (int ntl = 0; ntl < 4; ntl++)
                    mma_tf32(acc[mt][ntl], af[mt], bf[ntl]);
        }
        __syncthreads();
    }

    // ---- epilogue
#pragma unroll
    for (int mt = 0; mt < 4; mt++) {
        const int r0 = m0 + wm + mt * 16 + qid;
#pragma unroll
        for (int ntl = 0; ntl < 4; ntl++) {
            const int c0 = n0 + wn + ntl * 8 + cid * 2;
            float* d = acc[mt][ntl];
#pragma unroll
            for (int half = 0; half < 2; half++) {
                const int r = r0 + half * 8;
#pragma unroll
                for (int e = 0; e < 2; e++) {
                    const int n = c0 + e;
                    if (n < N) {
                        float v = d[half * 2 + e] * alpha;
                        if (bias) v += bias[n];
                        if (RELU) v = fmaxf(v, 0.f);
                        if (RND)  v = roundtf(v);
                        C[(size_t)r * ldc + n] = v;
                    }
                }
            }
        }
    }
#undef LOADG
}

// ---------------- row softmax (in place), rows of length 512 ----------------
// Writes tf32-rounded probabilities (consumer is exclusively the P@V GEMM).
__global__ void softmax_rows(float* __restrict__ p, int rows, int n)
{
    int row = blockIdx.x * blockDim.y + threadIdx.y;
    if (row >= rows) return;
    float* d = p + (size_t)row * n;
    int lane = threadIdx.x;

    float m = -INFINITY;
    for (int i = lane; i < n; i += 32) m = fmaxf(m, d[i]);
#pragma unroll
    for (int o = 16; o > 0; o >>= 1) m = fmaxf(m, __shfl_xor_sync(0xffffffffu, m, o));

    float s = 0.f;
    for (int i = lane; i < n; i += 32) s += __expf(d[i] - m);
#pragma unroll
    for (int o = 16; o > 0; o >>= 1) s += __shfl_xor_sync(0xffffffffu, s, o);

    float inv = 1.f / s;
    for (int i = lane; i < n; i += 32) d[i] = roundtf(__expf(d[i] - m) * inv);
}

// ---------------- CRF: normalizer + numerator (warp0), viterbi (warp1) ------
__global__ __launch_bounds__(64)
void crf_kernel(const float* __restrict__ em, const int* __restrict__ labels,
                const unsigned char* __restrict__ mask,
                const float* __restrict__ start_t, const float* __restrict__ end_t,
                const float* __restrict__ trans,
                float* __restrict__ out,
                float* __restrict__ num, float* __restrict__ den,
                float* __restrict__ msum)
{
    using namespace cfg;
    const int b = blockIdx.x;
    const int warp = threadIdx.x >> 5;
    const int lane = threadIdx.x & 31;
    const int j = lane < T ? lane : T - 1;

    __shared__ unsigned char hist[S - 1][T];
    __shared__ unsigned char path[S];

    float tc[T];
#pragma unroll
    for (int i = 0; i < T; i++) tc[i] = trans[i * T + j];

    const float* emb = em + (size_t)b * S * T;

    if (warp == 0) {
        float sc = start_t[j] + emb[j];
        for (int s = 1; s < S; s++) {
            float v[T];
#pragma unroll
            for (int i = 0; i < T; i++)
                v[i] = __shfl_sync(0xffffffffu, sc, i) + tc[i];
            float m = v[0];
#pragma unroll
            for (int i = 1; i < T; i++) m = fmaxf(m, v[i]);
            float sum = 0.f;
#pragma unroll
            for (int i = 0; i < T; i++) sum += __expf(v[i] - m);
            float nxt = m + __logf(sum) + emb[s * T + j];
            float mf = mask[b * S + s] ? 1.f : 0.f;
            sc = mf > 0.f ? nxt : sc;
        }
        float x = (lane < T) ? sc + end_t[j] : -INFINITY;
        float m = x;
#pragma unroll
        for (int o = 16; o > 0; o >>= 1) m = fmaxf(m, __shfl_xor_sync(0xffffffffu, m, o));
        float sum = (lane < T) ? __expf(x - m) : 0.f;
#pragma unroll
        for (int o = 16; o > 0; o >>= 1) sum += __shfl_xor_sync(0xffffffffu, sum, o);
        float d = m + __logf(sum);

        float part = 0.f, ms = 0.f;
        for (int s = lane; s < S; s += 32) ms += mask[b * S + s] ? 1.f : 0.f;
        for (int s = 1 + lane; s < S; s += 32) {
            int lp = labels[b * S + s - 1];
            int lc = labels[b * S + s];
            float mf = mask[b * S + s] ? 1.f : 0.f;
            part += (trans[lp * T + lc] + emb[s * T + lc]) * mf;
        }
#pragma unroll
        for (int o = 16; o > 0; o >>= 1) {
            part += __shfl_xor_sync(0xffffffffu, part, o);
            ms   += __shfl_xor_sync(0xffffffffu, ms, o);
        }
        if (lane == 0) {
            int se = (int)ms - 1;
            int l0 = labels[b * S + 0];
            int lt = labels[b * S + se];
            num[b]  = start_t[l0] + emb[l0] + part + end_t[lt];
            den[b]  = d;
            msum[b] = ms;
        }
    } else {
        float sc = start_t[j] + emb[j];
        for (int s = 1; s < S; s++) {
            float best = -INFINITY;
            int bi = 0;
#pragma unroll
            for (int i = 0; i < T; i++) {
                float vi = __shfl_sync(0xffffffffu, sc, i) + tc[i];
                if (vi > best) { best = vi; bi = i; }
            }
            if (lane < T) hist[s - 1][j] = (unsigned char)bi;
            sc = best + emb[s * T + j];
        }
        float x = (lane < T) ? sc + end_t[j] : -INFINITY;
        int idx = lane;
#pragma unroll
        for (int o = 16; o > 0; o >>= 1) {
            float ov = __shfl_down_sync(0xffffffffu, x, o);
            int   oi = __shfl_down_sync(0xffffffffu, idx, o);
            if (ov > x || (ov == x && oi < idx)) { x = ov; idx = oi; }
        }
        idx = __shfl_sync(0xffffffffu, idx, 0);
        __syncwarp();
        if (lane == 0) {
            int cur = idx;
            path[S - 1] = (unsigned char)cur;
            for (int s = S - 1; s >= 1; s--) {
                cur = hist[s - 1][cur];
                path[s - 1] = (unsigned char)cur;
            }
        }
        __syncwarp();
        for (int s = lane; s < S; s += 32)
            out[b * S + s] = (float)path[s];
    }
}

// ---------------- final scalar: -llh ----------------------------------------
__global__ void llh_kernel(const float* __restrict__ num, const float* __restrict__ den,
                           const float* __restrict__ msum, float* __restrict__ out)
{
    using namespace cfg;
    int lane = threadIdx.x;
    float v = (lane < B) ? num[lane] - den[lane] : 0.f;
    float m = (lane < B) ? msum[lane] : 0.f;
#pragma unroll
    for (int o = 16; o > 0; o >>= 1) {
        v += __shfl_xor_sync(0xffffffffu, v, o);
        m += __shfl_xor_sync(0xffffffffu, m, o);
    }
    if (lane == 0) out[3 * BS] = -(v / m);
}

// ---------------- seg head: log_softmax(dec @ ent_w^T + ent_b) --------------
__global__ __launch_bounds__(256)
void seg_kernel(const float* __restrict__ dec, const float* __restrict__ ent_w,
                const float* __restrict__ ent_b, float* __restrict__ out)
{
    using namespace cfg;
    int warp = threadIdx.x >> 5;
    int lane = threadIdx.x & 31;
    int row = blockIdx.x * 8 + warp;
    if (row >= BS) return;
    const float* d = dec + (size_t)row * E;

    float a0 = 0.f, a1 = 0.f;
    for (int k = lane * 4; k < E; k += 128) {
        float4 dv = *(const float4*)(d + k);
        float4 w0 = *(const float4*)(ent_w + k);
        float4 w1 = *(const float4*)(ent_w + E + k);
        a0 += dv.x * w0.x + dv.y * w0.y + dv.z * w0.z + dv.w * w0.w;
        a1 += dv.x * w1.x + dv.y * w1.y + dv.z * w1.z + dv.w * w1.w;
    }
#pragma unroll
    for (int o = 16; o > 0; o >>= 1) {
        a0 += __shfl_xor_sync(0xffffffffu, a0, o);
        a1 += __shfl_xor_sync(0xffffffffu, a1, o);
    }
    if (lane == 0) {
        float z0 = a0 + ent_b[0];
        float z1 = a1 + ent_b[1];
        float m = fmaxf(z0, z1);
        float lse = m + __logf(__expf(z0 - m) + __expf(z1 - m));
        out[BS + (size_t)row * 2 + 0] = z0 - lse;
        out[BS + (size_t)row * 2 + 1] = z1 - lse;
    }
}

// ---------------- host launch ------------------------------------------------
extern "C" void kernel_launch(void* const* d_in, const int* in_sizes, int n_in,
                              void* d_out, int out_size)
{
    using namespace cfg;
    const float* x       = (const float*)d_in[0];
    const int*   labels  = (const int*)d_in[1];
    const unsigned char* mask = (const unsigned char*)d_in[2];
    const float* Win     = (const float*)d_in[3];
    const float* bin     = (const float*)d_in[4];
    const float* Wout    = (const float*)d_in[5];
    const float* bout    = (const float*)d_in[6];
    const float* crf_w   = (const float*)d_in[7];
    const float* crf_b   = (const float*)d_in[8];
    const float* start_t = (const float*)d_in[9];
    const float* end_t   = (const float*)d_in[10];
    const float* trans   = (const float*)d_in[11];
    const float* ent_w   = (const float*)d_in[12];
    const float* ent_b   = (const float*)d_in[13];
    float* out = (float*)d_out;

    float *qkv, *scores, *attn, *dec, *em, *xr, *wr, *num, *den, *msum;
    cudaGetSymbolAddress((void**)&qkv,    g_qkv);
    cudaGetSymbolAddress((void**)&scores, g_scores);
    cudaGetSymbolAddress((void**)&attn,   g_attn);
    cudaGetSymbolAddress((void**)&dec,    g_dec);
    cudaGetSymbolAddress((void**)&em,     g_em);
    cudaGetSymbolAddress((void**)&xr,     g_xr);
    cudaGetSymbolAddress((void**)&wr,     g_wr);
    cudaGetSymbolAddress((void**)&num,    g_num);
    cudaGetSymbolAddress((void**)&den,    g_den);
    cudaGetSymbolAddress((void**)&msum,   g_msum);

    float* Win_r  = wr;                        // 3E*E
    float* Wout_r = wr + (size_t)3 * E * E;    // E*E
    float* crfw_r = wr + (size_t)4 * E * E;    // T*E

    // 0) pre-round GEMM inputs to tf32 (== rna at fragment load, hoisted)
    {
        int n4;
        n4 = (BS * E) / 4;
        round_tf32_kernel<<<(n4 + 255) / 256, 256>>>(x, xr, n4);
        n4 = (3 * E * E) / 4;
        round_tf32_kernel<<<(n4 + 255) / 256, 256>>>(Win, Win_r, n4);
        n4 = (E * E) / 4;
        round_tf32_kernel<<<(n4 + 255) / 256, 256>>>(Wout, Wout_r, n4);
        n4 = (T * E) / 4;
        round_tf32_kernel<<<(n4 + 255) / 256, 256>>>(crf_w, crfw_r, n4);
    }

    // 1) qkv = x @ Win^T + bin   (rounded output; consumers are GEMMs only)
    tgemm<true, false, false, true><<<dim3(12, 128, 1), 256>>>(
        xr, Win_r, qkv, bin, BS, 3 * E, E, E, E, 3 * E, 1.f,
        1, 0, 0, 0, 0, 0, 0);

    // 2) scores = Q K^T / 16   (raw output; softmax rounds)
    tgemm<true, false, false, false><<<dim3(4, 4, 64), 256>>>(
        qkv, qkv + E, scores, nullptr, S, S, HD, 3 * E, 3 * E, S, 1.f / 16.f,
        H, S * 3 * E, HD, S * 3 * E, HD, H * S * S, S * S);

    // 3) softmax over k (writes rounded probs)
    softmax_rows<<<(B * H * S) / 8, dim3(32, 8)>>>(scores, B * H * S, S);

    // 4) attn = P @ V   (rounded output; consumer is GEMM5 only)
    tgemm<false, false, false, true><<<dim3(2, 4, 64), 256>>>(
        scores, qkv + 2 * E, attn, nullptr, S, HD, S, S, 3 * E, E, 1.f,
        H, H * S * S, S * S, S * 3 * E, HD, S * E, HD);

    // 5) dec = relu(attn @ Wout^T + bout)   (fp32 output: feeds seg head)
    tgemm<true, true, false, false><<<dim3(4, 128, 1), 256>>>(
        attn, Wout_r, dec, bout, BS, E, E, E, E, E, 1.f,
        1, 0, 0, 0, 0, 0, 0);

    // 6) em = dec @ crf_w^T + crf_b   (dec unrounded -> CVT at load)
    tgemm<true, false, true, false><<<dim3(1, 128, 1), 256>>>(
        dec, crfw_r, em, crf_b, BS, T, E, E, E, T, 1.f,
        1, 0, 0, 0, 0, 0, 0);

    // 7) CRF
    crf_kernel<<<B, 64>>>(em, labels, mask, start_t, end_t, trans,
                          out, num, den, msum);

    // 8) scalar loss
    llh_kernel<<<1, 32>>>(num, den, msum, out);

    // 9) seg head
    seg_kernel<<<BS / 8, 256>>>(dec, ent_w, ent_b, out);
}

// round 10
// speedup vs baseline: 1.1604x; 1.1604x over previous
#include <cuda_runtime.h>
#include <math.h>

namespace cfg {
constexpr int B  = 32;
constexpr int S  = 512;
constexpr int E  = 512;
constexpr int T  = 24;
constexpr int H  = 2;
constexpr int HD = E / H;          // 256
constexpr int BS = B * S;          // 16384
}

// ---------------- scratch (static device globals; no allocation) ------------
__device__ float g_qkv[(size_t)cfg::B * cfg::S * 3 * cfg::E];
__device__ float g_scores[(size_t)cfg::B * cfg::H * cfg::S * cfg::S];
__device__ float g_attn[(size_t)cfg::B * cfg::S * cfg::E];
__device__ float g_dec [(size_t)cfg::B * cfg::S * cfg::E];
__device__ float g_em  [(size_t)cfg::B * cfg::S * cfg::T];
__device__ float g_num [cfg::B];
__device__ float g_den [cfg::B];
__device__ float g_msum[cfg::B];

// ---------------- helpers ----------------------------------------------------
__device__ __forceinline__ unsigned f2tf(unsigned rawf32) {
    unsigned u;
    asm("cvt.rna.tf32.f32 %0, %1;" : "=r"(u) : "f"(__uint_as_float(rawf32)));
    return u;
}

__device__ __forceinline__ void mma_tf32(float* d, const unsigned* a, const unsigned* b) {
    asm volatile(
        "mma.sync.aligned.m16n8k8.row.col.f32.tf32.tf32.f32 "
        "{%0,%1,%2,%3}, {%4,%5,%6,%7}, {%8,%9}, {%0,%1,%2,%3};"
        : "+f"(d[0]), "+f"(d[1]), "+f"(d[2]), "+f"(d[3])
        : "r"(a[0]), "r"(a[1]), "r"(a[2]), "r"(a[3]), "r"(b[0]), "r"(b[1]));
}

__device__ __forceinline__ void cp16(unsigned dst, const float* src, bool pred) {
    int sz = pred ? 16 : 0;
    asm volatile("cp.async.cg.shared.global [%0], [%1], 16, %2;"
                 :: "r"(dst), "l"(src), "r"(sz));
}
__device__ __forceinline__ void cp_commit() {
    asm volatile("cp.async.commit_group;");
}
template<int N0>
__device__ __forceinline__ void cp_wait() {
    asm volatile("cp.async.wait_group %0;" :: "n"(N0));
}

// ---------------- TF32 tensor-core GEMM (R6-exact config) --------------------
template<bool TRANSB, bool RELU>
__global__ __launch_bounds__(256, 2)
void tgemm(const float* __restrict__ A, const float* __restrict__ Bp,
           float* __restrict__ C, const float* __restrict__ bias,
           int M, int N, int K, int lda, int ldb, int ldc, float alpha,
           int HH, int sab, int sah, int sbb, int sbh, int scb, int sch)
{
    constexpr int BK    = 16;
    constexpr int ASTR  = 20;
    constexpr int BSTRT = 20;
    constexpr int BSTRN = 136;

    int z = blockIdx.z;
    A  += (size_t)(z / HH) * sab + (size_t)(z % HH) * sah;
    Bp += (size_t)(z / HH) * sbb + (size_t)(z % HH) * sbh;
    C  += (size_t)(z / HH) * scb + (size_t)(z % HH) * sch;

    __shared__ unsigned As[2][128 * ASTR];
    __shared__ unsigned Bs[2][128 * ASTR];

    const int tid  = threadIdx.x;
    const int warp = tid >> 5;
    const int lane = tid & 31;
    const int qid  = lane >> 2;
    const int cid  = lane & 3;

    const int m0 = blockIdx.y * 128;
    const int n0 = blockIdx.x * 128;
    const int wm = (warp >> 2) * 64;
    const int wn = (warp & 3) * 32;

    const int arow = tid >> 1;
    const int ak   = (tid & 1) * 8;
    const int bkk  = tid >> 4;
    const int bnn  = (tid & 15) * 8;

    float acc[4][4][4];
#pragma unroll
    for (int i = 0; i < 4; i++)
#pragma unroll
        for (int j = 0; j < 4; j++)
#pragma unroll
            for (int r = 0; r < 4; r++) acc[i][j][r] = 0.f;

    const int nt = K / BK;

    const unsigned as_d0 = (unsigned)__cvta_generic_to_shared(&As[0][arow * ASTR + ak]);
    const unsigned as_d1 = (unsigned)__cvta_generic_to_shared(&As[1][arow * ASTR + ak]);
    unsigned bs_d0, bs_d1;
    if (TRANSB) {
        bs_d0 = (unsigned)__cvta_generic_to_shared(&Bs[0][arow * BSTRT + ak]);
        bs_d1 = (unsigned)__cvta_generic_to_shared(&Bs[1][arow * BSTRT + ak]);
    } else {
        bs_d0 = (unsigned)__cvta_generic_to_shared(&Bs[0][bkk * BSTRN + bnn]);
        bs_d1 = (unsigned)__cvta_generic_to_shared(&Bs[1][bkk * BSTRN + bnn]);
    }
    const bool bval = TRANSB ? (n0 + arow < N) : (n0 + bnn < N);

#define LOADG(k0, buf)                                                         \
    {                                                                          \
        const float* Ap = A + (size_t)(m0 + arow) * lda + (k0) + ak;           \
        unsigned ad = (buf) ? as_d1 : as_d0;                                   \
        cp16(ad,      Ap,     true);                                           \
        cp16(ad + 16, Ap + 4, true);                                           \
        unsigned bd = (buf) ? bs_d1 : bs_d0;                                   \
        if (TRANSB) {                                                          \
            const float* Bq = Bp + (size_t)(n0 + arow) * ldb + (k0) + ak;      \
            cp16(bd,      Bq,     bval);                                       \
            cp16(bd + 16, Bq + 4, bval);                                       \
        } else {                                                               \
            const float* Bq = Bp + (size_t)((k0) + bkk) * ldb + n0 + bnn;      \
            cp16(bd,      Bq,     bval);                                       \
            cp16(bd + 16, Bq + 4, bval);                                       \
        }                                                                      \
    }

    LOADG(0, 0);
    cp_commit();

    for (int t = 0; t < nt; t++) {
        const int cur = t & 1;
        if (t + 1 < nt) LOADG((t + 1) * BK, cur ^ 1);
        cp_commit();
        cp_wait<1>();
        __syncthreads();

        const unsigned* Ab = As[cur];
        const unsigned* Bb = Bs[cur];
#pragma unroll
        for (int ks = 0; ks < 2; ks++) {
            const int k0 = ks * 8;
            unsigned af[4][4], bf[4][2];
#pragma unroll
            for (int mt = 0; mt < 4; mt++) {
                const int rb = wm + mt * 16 + qid;
                af[mt][0] = f2tf(Ab[(rb    ) * ASTR + k0 + cid]);
                af[mt][1] = f2tf(Ab[(rb + 8) * ASTR + k0 + cid]);
                af[mt][2] = f2tf(Ab[(rb    ) * ASTR + k0 + cid + 4]);
                af[mt][3] = f2tf(Ab[(rb + 8) * ASTR + k0 + cid + 4]);
            }
#pragma unroll
            for (int ntl = 0; ntl < 4; ntl++) {
                const int nb = wn + ntl * 8 + qid;
                if (TRANSB) {
                    bf[ntl][0] = f2tf(Bb[nb * BSTRT + k0 + cid]);
                    bf[ntl][1] = f2tf(Bb[nb * BSTRT + k0 + cid + 4]);
                } else {
                    bf[ntl][0] = f2tf(Bb[(k0 + cid    ) * BSTRN + nb]);
                    bf[ntl][1] = f2tf(Bb[(k0 + cid + 4) * BSTRN + nb]);
                }
            }
#pragma unroll
            for (int mt = 0; mt < 4; mt++)
#pragma unroll
                for (int ntl = 0; ntl < 4; ntl++)
                    mma_tf32(acc[mt][ntl], af[mt], bf[ntl]);
        }
        __syncthreads();
    }

#pragma unroll
    for (int mt = 0; mt < 4; mt++) {
        const int r0 = m0 + wm + mt * 16 + qid;
#pragma unroll
        for (int ntl = 0; ntl < 4; ntl++) {
            const int c0 = n0 + wn + ntl * 8 + cid * 2;
            float* d = acc[mt][ntl];
#pragma unroll
            for (int half = 0; half < 2; half++) {
                const int r = r0 + half * 8;
#pragma unroll
                for (int e = 0; e < 2; e++) {
                    const int n = c0 + e;
                    if (n < N) {
                        float v = d[half * 2 + e] * alpha;
                        if (bias) v += bias[n];
                        if (RELU) v = fmaxf(v, 0.f);
                        C[(size_t)r * ldc + n] = v;
                    }
                }
            }
        }
    }
#undef LOADG
}

// ---------------- row softmax, register-resident (rows of 512) ---------------
__global__ void softmax_rows(float* __restrict__ p, int rows)
{
    constexpr int N = 512;
    int row = blockIdx.x * blockDim.y + threadIdx.y;
    if (row >= rows) return;
    float* d = p + (size_t)row * N;
    int lane = threadIdx.x;

    // 16 elements per lane: 4x float4, stride 128 floats
    float4 v[4];
#pragma unroll
    for (int c = 0; c < 4; c++)
        v[c] = *(const float4*)(d + lane * 4 + c * 128);

    float m = -INFINITY;
#pragma unroll
    for (int c = 0; c < 4; c++) {
        m = fmaxf(m, fmaxf(fmaxf(v[c].x, v[c].y), fmaxf(v[c].z, v[c].w)));
    }
#pragma unroll
    for (int o = 16; o > 0; o >>= 1) m = fmaxf(m, __shfl_xor_sync(0xffffffffu, m, o));

    float s = 0.f;
#pragma unroll
    for (int c = 0; c < 4; c++) {
        v[c].x = __expf(v[c].x - m); v[c].y = __expf(v[c].y - m);
        v[c].z = __expf(v[c].z - m); v[c].w = __expf(v[c].w - m);
        s += (v[c].x + v[c].y) + (v[c].z + v[c].w);
    }
#pragma unroll
    for (int o = 16; o > 0; o >>= 1) s += __shfl_xor_sync(0xffffffffu, s, o);

    float inv = 1.f / s;
#pragma unroll
    for (int c = 0; c < 4; c++) {
        v[c].x *= inv; v[c].y *= inv; v[c].z *= inv; v[c].w *= inv;
        *(float4*)(d + lane * 4 + c * 128) = v[c];
    }
}

// ---------------- CRF: normalizer + numerator (warp0), viterbi (warp1) ------
__global__ __launch_bounds__(64)
void crf_kernel(const float* __restrict__ em, const int* __restrict__ labels,
                const unsigned char* __restrict__ mask,
                const float* __restrict__ start_t, const float* __restrict__ end_t,
                const float* __restrict__ trans,
                float* __restrict__ out,
                float* __restrict__ num, float* __restrict__ den,
                float* __restrict__ msum)
{
    using namespace cfg;
    const int b = blockIdx.x;
    const int warp = threadIdx.x >> 5;
    const int lane = threadIdx.x & 31;
    const int j = lane < T ? lane : T - 1;

    __shared__ unsigned char hist[S - 1][T];
    __shared__ unsigned char path[S];

    float tc[T];
#pragma unroll
    for (int i = 0; i < T; i++) tc[i] = trans[i * T + j];

    const float* emb = em + (size_t)b * S * T;

    if (warp == 0) {
        // ---------- forward algorithm via shared exp trick ----------
        // nxt_j = M + log(sum_i exp(sc_i - M) * exp(t_ij)) + em_j
        float et[T];
#pragma unroll
        for (int i = 0; i < T; i++) et[i] = __expf(tc[i]);

        float sc = start_t[j] + emb[j];
        float e_cur = emb[T + j];
        for (int s = 1; s < S; s++) {
            float e_next = (s + 1 < S) ? emb[(s + 1) * T + j] : 0.f;
            float mk = mask[b * S + s] ? 1.f : 0.f;

            float M = sc;
#pragma unroll
            for (int o = 16; o > 0; o >>= 1) M = fmaxf(M, __shfl_xor_sync(0xffffffffu, M, o));
            float p = __expf(sc - M);
            float s0 = 0.f, s1 = 0.f, s2 = 0.f, s3 = 0.f;
#pragma unroll
            for (int i = 0; i < T; i += 4) {
                s0 = fmaf(__shfl_sync(0xffffffffu, p, i    ), et[i    ], s0);
                s1 = fmaf(__shfl_sync(0xffffffffu, p, i + 1), et[i + 1], s1);
                s2 = fmaf(__shfl_sync(0xffffffffu, p, i + 2), et[i + 2], s2);
                s3 = fmaf(__shfl_sync(0xffffffffu, p, i + 3), et[i + 3], s3);
            }
            float inner = (s0 + s1) + (s2 + s3);
            float nxt = M + __logf(inner) + e_cur;
            sc = mk > 0.f ? nxt : sc;
            e_cur = e_next;
        }
        float x = (lane < T) ? sc + end_t[j] : -INFINITY;
        float m = x;
#pragma unroll
        for (int o = 16; o > 0; o >>= 1) m = fmaxf(m, __shfl_xor_sync(0xffffffffu, m, o));
        float sum = (lane < T) ? __expf(x - m) : 0.f;
#pragma unroll
        for (int o = 16; o > 0; o >>= 1) sum += __shfl_xor_sync(0xffffffffu, sum, o);
        float d = m + __logf(sum);

        // ---------- numerator + mask sum ----------
        float part = 0.f, ms = 0.f;
        for (int s = lane; s < S; s += 32) ms += mask[b * S + s] ? 1.f : 0.f;
        for (int s = 1 + lane; s < S; s += 32) {
            int lp = labels[b * S + s - 1];
            int lc = labels[b * S + s];
            float mf = mask[b * S + s] ? 1.f : 0.f;
            part += (trans[lp * T + lc] + emb[s * T + lc]) * mf;
        }
#pragma unroll
        for (int o = 16; o > 0; o >>= 1) {
            part += __shfl_xor_sync(0xffffffffu, part, o);
            ms   += __shfl_xor_sync(0xffffffffu, ms, o);
        }
        if (lane == 0) {
            int se = (int)ms - 1;
            int l0 = labels[b * S + 0];
            int lt = labels[b * S + se];
            num[b]  = start_t[l0] + emb[l0] + part + end_t[lt];
            den[b]  = d;
            msum[b] = ms;
        }
    } else {
        // ---------- viterbi (tree argmax, tie -> lowest index) ----------
        float sc = start_t[j] + emb[j];
        float e_cur = emb[T + j];
        for (int s = 1; s < S; s++) {
            float e_next = (s + 1 < S) ? emb[(s + 1) * T + j] : 0.f;

            float bv[12]; int bi[12];
            // level 0: 24 -> 12 (merge pairs (2i, 2i+1); lower index first)
#pragma unroll
            for (int i = 0; i < 12; i++) {
                float va = __shfl_sync(0xffffffffu, sc, 2 * i    ) + tc[2 * i    ];
                float vb = __shfl_sync(0xffffffffu, sc, 2 * i + 1) + tc[2 * i + 1];
                bool gt = vb > va;
                bv[i] = gt ? vb : va;
                bi[i] = gt ? 2 * i + 1 : 2 * i;
            }
            // 12 -> 6 -> 3
#pragma unroll
            for (int i = 0; i < 6; i++) {
                bool gt = bv[2 * i + 1] > bv[2 * i];
                bv[i] = gt ? bv[2 * i + 1] : bv[2 * i];
                bi[i] = gt ? bi[2 * i + 1] : bi[2 * i];
            }
#pragma unroll
            for (int i = 0; i < 3; i++) {
                bool gt = bv[2 * i + 1] > bv[2 * i];
                bv[i] = gt ? bv[2 * i + 1] : bv[2 * i];
                bi[i] = gt ? bi[2 * i + 1] : bi[2 * i];
            }
            // 3 -> 1
            bool g1 = bv[1] > bv[0];
            float v01 = g1 ? bv[1] : bv[0];
            int   i01 = g1 ? bi[1] : bi[0];
            bool g2 = bv[2] > v01;
            float best = g2 ? bv[2] : v01;
            int   bix  = g2 ? bi[2] : i01;

            if (lane < T) hist[s - 1][j] = (unsigned char)bix;
            sc = best + e_cur;
            e_cur = e_next;
        }
        float x = (lane < T) ? sc + end_t[j] : -INFINITY;
        int idx = lane;
#pragma unroll
        for (int o = 16; o > 0; o >>= 1) {
            float ov = __shfl_down_sync(0xffffffffu, x, o);
            int   oi = __shfl_down_sync(0xffffffffu, idx, o);
            if (ov > x || (ov == x && oi < idx)) { x = ov; idx = oi; }
        }
        idx = __shfl_sync(0xffffffffu, idx, 0);
        __syncwarp();
        if (lane == 0) {
            int cur = idx;
            path[S - 1] = (unsigned char)cur;
            for (int s = S - 1; s >= 1; s--) {
                cur = hist[s - 1][cur];
                path[s - 1] = (unsigned char)cur;
            }
        }
        __syncwarp();
        for (int s = lane; s < S; s += 32)
            out[b * S + s] = (float)path[s];
    }
}

// ---------------- final scalar: -llh ----------------------------------------
__global__ void llh_kernel(const float* __restrict__ num, const float* __restrict__ den,
                           const float* __restrict__ msum, float* __restrict__ out)
{
    using namespace cfg;
    int lane = threadIdx.x;
    float v = (lane < B) ? num[lane] - den[lane] : 0.f;
    float m = (lane < B) ? msum[lane] : 0.f;
#pragma unroll
    for (int o = 16; o > 0; o >>= 1) {
        v += __shfl_xor_sync(0xffffffffu, v, o);
        m += __shfl_xor_sync(0xffffffffu, m, o);
    }
    if (lane == 0) out[3 * BS] = -(v / m);
}

// ---------------- seg head: log_softmax(dec @ ent_w^T + ent_b) --------------
__global__ __launch_bounds__(256)
void seg_kernel(const float* __restrict__ dec, const float* __restrict__ ent_w,
                const float* __restrict__ ent_b, float* __restrict__ out)
{
    using namespace cfg;
    int warp = threadIdx.x >> 5;
    int lane = threadIdx.x & 31;
    int row = blockIdx.x * 8 + warp;
    if (row >= BS) return;
    const float* d = dec + (size_t)row * E;

    float a0 = 0.f, a1 = 0.f;
    for (int k = lane * 4; k < E; k += 128) {
        float4 dv = *(const float4*)(d + k);
        float4 w0 = *(const float4*)(ent_w + k);
        float4 w1 = *(const float4*)(ent_w + E + k);
        a0 += dv.x * w0.x + dv.y * w0.y + dv.z * w0.z + dv.w * w0.w;
        a1 += dv.x * w1.x + dv.y * w1.y + dv.z * w1.z + dv.w * w1.w;
    }
#pragma unroll
    for (int o = 16; o > 0; o >>= 1) {
        a0 += __shfl_xor_sync(0xffffffffu, a0, o);
        a1 += __shfl_xor_sync(0xffffffffu, a1, o);
    }
    if (lane == 0) {
        float z0 = a0 + ent_b[0];
        float z1 = a1 + ent_b[1];
        float m = fmaxf(z0, z1);
        float lse = m + __logf(__expf(z0 - m) + __expf(z1 - m));
        out[BS + (size_t)row * 2 + 0] = z0 - lse;
        out[BS + (size_t)row * 2 + 1] = z1 - lse;
    }
}

// ---------------- host launch ------------------------------------------------
extern "C" void kernel_launch(void* const* d_in, const int* in_sizes, int n_in,
                              void* d_out, int out_size)
{
    using namespace cfg;
    const float* x       = (const float*)d_in[0];
    const int*   labels  = (const int*)d_in[1];
    const unsigned char* mask = (const unsigned char*)d_in[2];
    const float* Win     = (const float*)d_in[3];
    const float* bin     = (const float*)d_in[4];
    const float* Wout    = (const float*)d_in[5];
    const float* bout    = (const float*)d_in[6];
    const float* crf_w   = (const float*)d_in[7];
    const float* crf_b   = (const float*)d_in[8];
    const float* start_t = (const float*)d_in[9];
    const float* end_t   = (const float*)d_in[10];
    const float* trans   = (const float*)d_in[11];
    const float* ent_w   = (const float*)d_in[12];
    const float* ent_b   = (const float*)d_in[13];
    float* out = (float*)d_out;

    float *qkv, *scores, *attn, *dec, *em, *num, *den, *msum;
    cudaGetSymbolAddress((void**)&qkv,    g_qkv);
    cudaGetSymbolAddress((void**)&scores, g_scores);
    cudaGetSymbolAddress((void**)&attn,   g_attn);
    cudaGetSymbolAddress((void**)&dec,    g_dec);
    cudaGetSymbolAddress((void**)&em,     g_em);
    cudaGetSymbolAddress((void**)&num,    g_num);
    cudaGetSymbolAddress((void**)&den,    g_den);
    cudaGetSymbolAddress((void**)&msum,   g_msum);

    // 1) qkv = x @ Win^T + bin          (16384 x 1536 x 512)
    tgemm<true, false><<<dim3(12, 128, 1), 256>>>(
        x, Win, qkv, bin, BS, 3 * E, E, E, E, 3 * E, 1.f,
        1, 0, 0, 0, 0, 0, 0);

    // 2) scores = Q K^T / 16            (batched 64: 512 x 512 x 256)
    tgemm<true, false><<<dim3(4, 4, 64), 256>>>(
        qkv, qkv + E, scores, nullptr, S, S, HD, 3 * E, 3 * E, S, 1.f / 16.f,
        H, S * 3 * E, HD, S * 3 * E, HD, H * S * S, S * S);

    // 3) softmax over k
    softmax_rows<<<(B * H * S) / 8, dim3(32, 8)>>>(scores, B * H * S);

    // 4) attn = P @ V                   (batched 64: 512 x 256 x 512)
    tgemm<false, false><<<dim3(2, 4, 64), 256>>>(
        scores, qkv + 2 * E, attn, nullptr, S, HD, S, S, 3 * E, E, 1.f,
        H, H * S * S, S * S, S * 3 * E, HD, S * E, HD);

    // 5) dec = relu(attn @ Wout^T + bout)
    tgemm<true, true><<<dim3(4, 128, 1), 256>>>(
        attn, Wout, dec, bout, BS, E, E, E, E, E, 1.f,
        1, 0, 0, 0, 0, 0, 0);

    // 6) em = dec @ crf_w^T + crf_b
    tgemm<true, false><<<dim3(1, 128, 1), 256>>>(
        dec, crf_w, em, crf_b, BS, T, E, E, E, T, 1.f,
        1, 0, 0, 0, 0, 0, 0);

    // 7) CRF
    crf_kernel<<<B, 64>>>(em, labels, mask, start_t, end_t, trans,
                          out, num, den, msum);

    // 8) scalar loss
    llh_kernel<<<1, 32>>>(num, den, msum, out);

    // 9) seg head
    seg_kernel<<<BS / 8, 256>>>(dec, ent_w, ent_b, out);
}